// round 13
// baseline (speedup 1.0000x reference)
#include <cuda_runtime.h>
#include <math.h>
#include <cstdint>

#define BB 64
#define LL 2048
#define HH 256
#define BLH (BB*LL*HH)

// Scratch (device globals: allocation-free per harness rules)
__device__ float g_Z[BLH];     // input-transform term per (b,t,h)
__device__ float g_H0[BLH];    // layer-0 hidden states

// ---------------------------------------------------------------------------
// PTX helpers (R12-proven set)
__device__ __forceinline__ uint32_t s2u(const void* p) {
    uint32_t a;
    asm("{ .reg .u64 t; cvta.to.shared.u64 t, %1; cvt.u32.u64 %0, t; }"
        : "=r"(a) : "l"(p));
    return a;
}
__device__ __forceinline__ uint32_t mapa_u32(uint32_t addr, uint32_t rank) {
    uint32_t r;
    asm("mapa.shared::cluster.u32 %0, %1, %2;" : "=r"(r) : "r"(addr), "r"(rank));
    return r;
}
__device__ __forceinline__ void mbar_init(uint32_t mbar, uint32_t count) {
    asm volatile("mbarrier.init.shared::cta.b64 [%0], %1;" :: "r"(mbar), "r"(count) : "memory");
}
__device__ __forceinline__ void mbar_expect_tx(uint32_t mbar, uint32_t bytes) {
    asm volatile("mbarrier.arrive.expect_tx.shared::cta.b64 _, [%0], %1;"
                 :: "r"(mbar), "r"(bytes) : "memory");
}
// Async remote store into peer CTA's SMEM; data + completion travel together,
// completion counted (in bytes) on the peer's mbarrier. No fence, no arrive.
__device__ __forceinline__ void st_async_u32(uint32_t raddr, uint32_t v, uint32_t rmbar) {
    asm volatile("st.async.shared::cluster.mbarrier::complete_tx::bytes.b32 [%0], %1, [%2];"
                 :: "r"(raddr), "r"(v), "r"(rmbar) : "memory");
}
__device__ __forceinline__ void mbar_wait_parity(uint32_t mbar, uint32_t parity) {
    uint32_t done;
    asm volatile(
        "{\n\t.reg .pred p;\n\t"
        "mbarrier.try_wait.parity.acquire.cluster.shared::cta.b64 p, [%1], %2;\n\t"
        "selp.b32 %0, 1, 0, p;\n\t}"
        : "=r"(done) : "r"(mbar), "r"(parity) : "memory");
    if (!done) {
        asm volatile(
            "{\n\t.reg .pred P1;\n\t"
            "WL_%=:\n\t"
            "mbarrier.try_wait.parity.acquire.cluster.shared::cta.b64 P1, [%0], %1, 0x989680;\n\t"
            "@P1 bra.uni WD_%=;\n\t"
            "bra.uni WL_%=;\n\t"
            "WD_%=:\n\t}"
            :: "r"(mbar), "r"(parity) : "memory");
    }
}
__device__ __forceinline__ void cluster_sync() {
    asm volatile("barrier.cluster.arrive.aligned;" ::: "memory");
    asm volatile("barrier.cluster.wait.aligned;" ::: "memory");
}

// Branch-free fast tanh: 1 - 2/(exp(2x)+1). Saturates correctly at +-inf.
__device__ __forceinline__ float tanh_fast(float x) {
    const float e = __expf(2.0f * x);
    return 1.0f - __fdividef(2.0f, e + 1.0f);
}

// ---------------------------------------------------------------------------
// GEMM + bias (R8-proven; ~fp32 SIMT peak): Out[r][j] = In[r]·W[:,j]+bi[j]+bh[j]
// M = 131072, N = K = 256. Tile 128x128x8, 256 threads, 8x8/thread.
__global__ __launch_bounds__(256) void gemm_bias(
        const float* __restrict__ In, const float* __restrict__ W,
        const float* __restrict__ bi, const float* __restrict__ bh,
        float* __restrict__ Out)
{
    __shared__ float As[8][128];
    __shared__ float Bs[8][128];
    const int tid  = threadIdx.x;
    const int mblk = blockIdx.x * 128;
    const int nblk = blockIdx.y * 128;
    const int tx = tid & 15, ty = tid >> 4;

    const int ar = tid >> 1;
    const int ak = (tid & 1) * 4;
    const int bk = tid >> 5;
    const int bc = (tid & 31) * 4;

    const float* Arow = In + (size_t)(mblk + ar) * HH;
    float4 a_next = *(const float4*)(Arow + ak);
    float4 b_next = *(const float4*)(W + (size_t)bk * HH + nblk + bc);

    float acc[8][8];
#pragma unroll
    for (int i = 0; i < 8; i++)
#pragma unroll
        for (int j = 0; j < 8; j++) acc[i][j] = 0.f;

    for (int kt = 0; kt < 32; kt++) {
        As[ak + 0][ar] = a_next.x;
        As[ak + 1][ar] = a_next.y;
        As[ak + 2][ar] = a_next.z;
        As[ak + 3][ar] = a_next.w;
        *(float4*)&Bs[bk][bc] = b_next;
        __syncthreads();
        if (kt < 31) {
            a_next = *(const float4*)(Arow + (kt + 1) * 8 + ak);
            b_next = *(const float4*)(W + (size_t)((kt + 1) * 8 + bk) * HH + nblk + bc);
        }
#pragma unroll
        for (int kk = 0; kk < 8; kk++) {
            float a[8], b[8];
            *(float4*)&a[0] = *(const float4*)&As[kk][ty * 8];
            *(float4*)&a[4] = *(const float4*)&As[kk][ty * 8 + 4];
            *(float4*)&b[0] = *(const float4*)&Bs[kk][tx * 8];
            *(float4*)&b[4] = *(const float4*)&Bs[kk][tx * 8 + 4];
#pragma unroll
            for (int i = 0; i < 8; i++)
#pragma unroll
                for (int j = 0; j < 8; j++) acc[i][j] += a[i] * b[j];
        }
        __syncthreads();
    }

#pragma unroll
    for (int i = 0; i < 8; i++) {
        const size_t r = (size_t)(mblk + ty * 8 + i);
#pragma unroll
        for (int j = 0; j < 8; j += 4) {
            const int c = nblk + tx * 8 + j;
            float4 v;
            v.x = acc[i][j + 0] + bi[c + 0] + bh[c + 0];
            v.y = acc[i][j + 1] + bi[c + 1] + bh[c + 1];
            v.z = acc[i][j + 2] + bi[c + 2] + bh[c + 2];
            v.w = acc[i][j + 3] + bi[c + 3] + bh[c + 3];
            *(float4*)(Out + r * HH + c) = v;
        }
    }
}

// ---------------------------------------------------------------------------
// Recurrence pass v4: pair-split columns, shfl_xor(1) merge, ONE bar/step.
//   Cluster of 2 CTAs per batch; CTA rank r owns cols [r*128,+128).
//   Warp w owns cols [w*16,+16). Lane l -> col (w*16 + (l>>1)),
//   k-subrange (l&1): within each 128-wide phase, thread covers 64 k's.
//   Per thread 128 FFMA/step (4 acc chains); shfl_xor(1) merges the lane
//   pair -> full dot product on even lanes. No sacc, no reduction roundtrip.
//   Exchange (R12-proven): st.async + complete_tx into peer's double-
//   buffered recvbuf; expect_tx re-armed race-free (pre-posted for data 0/1,
//   re-arm for data t+1 happens before our send of h_t which gates peer's
//   t+1 production). ONE __syncthreads per step (publish -> next phase 1).
__global__ __launch_bounds__(256, 1) __cluster_dims__(2, 1, 1)
void rnn_pass(
        const float* __restrict__ Z,    // [B,L,H]
        const float* __restrict__ Wh,   // [H,H]
        const float* __restrict__ h0,   // [B,H]
        float* __restrict__ Out,        // [B,L,H]
        float* __restrict__ hfinal)     // [B,H] or null
{
    const int b     = blockIdx.x >> 1;
    const int half  = blockIdx.x & 1;            // == cluster rank
    const int jbase = half << 7;
    const int peerbase = 128 - jbase;
    const int tid  = threadIdx.x;
    const int w    = tid >> 5;
    const int lane = tid & 31;
    const int cl   = (w << 4) + (lane >> 1);     // col within own block (0..127)
    const int kh   = lane & 1;                   // k-subrange within phase (0/1)
    const int colabs = jbase + cl;
    const bool pub = (kh == 0);                  // even lanes publish

    __shared__ float sh_h[256];                  // own half live; peer half only at t=0
    __shared__ float recvbuf[2][128];            // peer halves, double-buffered
    __shared__ uint64_t mbar[2];

    const uint32_t mbar0 = s2u(&mbar[0]);
    const uint32_t mbar1 = s2u(&mbar[1]);
    const uint32_t rb0   = s2u(&recvbuf[0][0]);
    const uint32_t rb1   = s2u(&recvbuf[1][0]);
    const uint32_t prank = (uint32_t)(half ^ 1);
    const uint32_t p_rb[2]   = { mapa_u32(rb0 + (uint32_t)cl * 4u, prank),
                                 mapa_u32(rb1 + (uint32_t)cl * 4u, prank) };
    const uint32_t l_mbar[2] = { mbar0, mbar1 };
    const uint32_t p_mbar[2] = { mapa_u32(mbar0, prank), mapa_u32(mbar1, prank) };

    if (tid == 0) {
        mbar_init(mbar0, 1);                 // 1 arrival = the expect_tx itself
        mbar_init(mbar1, 1);
        mbar_expect_tx(mbar0, 512);          // data 0 (arrives into buf 0)
        mbar_expect_tx(mbar1, 512);          // data 1 (arrives into buf 1)
    }

    // Weights: 64 own-half + 64 peer-half k's for this thread's column.
    float wown[64], wpeer[64];
#pragma unroll
    for (int i = 0; i < 64; i++)
        wown[i] = Wh[(size_t)(jbase + kh * 64 + i) * HH + colabs];
#pragma unroll
    for (int i = 0; i < 64; i++)
        wpeer[i] = Wh[(size_t)(peerbase + kh * 64 + i) * HH + colabs];

    sh_h[tid] = h0[b * HH + tid];
    __syncthreads();
    cluster_sync();   // both CTAs' mbarrier init + initial expects visible before any send

    // Z prefetch (one step ahead); publishing (even) lanes only.
    float zv = pub ? Z[((size_t)b * LL + 0) * HH + colabs] : 0.f;

    for (int t = 0; t < LL; t++) {
        // Prefetch next step's Z while we compute this one.
        float zv_next = 0.f;
        if (t + 1 < LL && pub)
            zv_next = Z[((size_t)b * LL + (t + 1)) * HH + colabs];

        float a0 = 0.f, a1 = 0.f, a2 = 0.f, a3 = 0.f;

        // ---- phase 1: own k-half, this thread's 64 k's (local, no wait) ----
        {
            const float4* h4 = (const float4*)(sh_h + jbase + kh * 64);
#pragma unroll
            for (int m = 0; m < 16; m++) {
                const float4 hv4 = h4[m];
                a0 += wown[4 * m + 0] * hv4.x;
                a1 += wown[4 * m + 1] * hv4.y;
                a2 += wown[4 * m + 2] * hv4.z;
                a3 += wown[4 * m + 3] * hv4.w;
            }
        }

        // ---- wait for peer half of h_{t-1}; re-arm expect for data t+1 ----
        const float4* s4;
        if (t > 0) {
            mbar_wait_parity(l_mbar[(t - 1) & 1], ((t - 1) >> 1) & 1);
            if (t <= LL - 3 && tid == 0)
                mbar_expect_tx(l_mbar[(t - 1) & 1], 512);
            s4 = (const float4*)(&recvbuf[(t - 1) & 1][kh * 64]);
        } else {
            s4 = (const float4*)(sh_h + peerbase + kh * 64);
        }

        // ---- phase 2: peer k-half, this thread's 64 k's ----
        {
#pragma unroll
            for (int m = 0; m < 16; m++) {
                const float4 hv4 = s4[m];
                a0 += wpeer[4 * m + 0] * hv4.x;
                a1 += wpeer[4 * m + 1] * hv4.y;
                a2 += wpeer[4 * m + 2] * hv4.z;
                a3 += wpeer[4 * m + 3] * hv4.w;
            }
        }

        // ---- merge lane pair via shfl + tanh + publish ----
        float s = (a0 + a1) + (a2 + a3);
        s += __shfl_xor_sync(0xffffffffu, s, 1);
        if (pub) {
            const float hv = tanh_fast(s + zv);
            sh_h[colabs] = hv;                                  // own half for t+1
            if (t < LL - 1)
                st_async_u32(p_rb[t & 1], __float_as_uint(hv),
                             p_mbar[t & 1]);                    // async push+complete
            Out[((size_t)b * LL + t) * HH + colabs] = hv;       // result (off chain)
        }
        zv = zv_next;
        __syncthreads();   // publish(t) visible to all warps' phase 1 of t+1
    }

    if (hfinal && pub)
        hfinal[b * HH + colabs] = sh_h[colabs];

    cluster_sync();   // no CTA exits while peer stores may be in flight
}

// ---------------------------------------------------------------------------
extern "C" void kernel_launch(void* const* d_in, const int* in_sizes, int n_in,
                              void* d_out, int out_size) {
    const float* x  = (const float*)d_in[0];   // [B,L,H]
    const float* h0 = (const float*)d_in[1];   // [NL,B,H]
    const float* WI = (const float*)d_in[2];   // [NL,H,H]
    const float* BI = (const float*)d_in[3];   // [NL,H]
    const float* WH = (const float*)d_in[4];   // [NL,H,H]
    const float* BH = (const float*)d_in[5];   // [NL,H]
    float* out = (float*)d_out;

    float *gZ = nullptr, *gH0 = nullptr;
    cudaGetSymbolAddress((void**)&gZ, g_Z);
    cudaGetSymbolAddress((void**)&gH0, g_H0);

    const dim3 ggrid(BB * LL / 128, HH / 128);  // (1024, 2)

    const bool haveMain  = (out_size >= BLH);
    const bool haveFinal = (out_size >= BLH + 2 * BB * HH);
    float* out2 = haveMain ? out : gZ;
    float* hf0  = haveFinal ? (out + BLH) : (haveMain ? nullptr : out);
    float* hf1  = haveFinal ? (out + BLH + BB * HH)
                            : (haveMain ? nullptr : out + BB * HH);

    // Phase A: Z0 = X @ WI0 + BI0 + BH0
    gemm_bias<<<ggrid, 256>>>(x, WI, BI, BH, gZ);
    // Phase B: layer-0 recurrence (64 clusters x 2 CTAs)
    rnn_pass<<<2 * BB, 256>>>(gZ, WH, h0, gH0, hf0);
    // Phase C: Z1 = H0 @ WI1 + BI1 + BH1
    gemm_bias<<<ggrid, 256>>>(gH0, WI + HH * HH, BI + HH, BH + HH, gZ);
    // Phase D: layer-1 recurrence -> output
    rnn_pass<<<2 * BB, 256>>>(gZ, WH + HH * HH, h0 + BB * HH, out2, hf1);
}

// round 15
// speedup vs baseline: 2.1866x; 2.1866x over previous
#include <cuda_runtime.h>
#include <math.h>
#include <cstdint>

#define BB 64
#define LL 2048
#define HH 256
#define BLH (BB*LL*HH)

// Scratch (device globals: allocation-free per harness rules)
__device__ float g_Z[BLH];     // input-transform term per (b,t,h)
__device__ float g_H0[BLH];    // layer-0 hidden states

// ---------------------------------------------------------------------------
// PTX helpers (R12-proven set; NO raw mbarrier-word reads — R14 faulted on that)
__device__ __forceinline__ uint32_t s2u(const void* p) {
    uint32_t a;
    asm("{ .reg .u64 t; cvta.to.shared.u64 t, %1; cvt.u32.u64 %0, t; }"
        : "=r"(a) : "l"(p));
    return a;
}
__device__ __forceinline__ uint32_t mapa_u32(uint32_t addr, uint32_t rank) {
    uint32_t r;
    asm("mapa.shared::cluster.u32 %0, %1, %2;" : "=r"(r) : "r"(addr), "r"(rank));
    return r;
}
__device__ __forceinline__ void mbar_init(uint32_t mbar, uint32_t count) {
    asm volatile("mbarrier.init.shared::cta.b64 [%0], %1;" :: "r"(mbar), "r"(count) : "memory");
}
__device__ __forceinline__ void mbar_expect_tx(uint32_t mbar, uint32_t bytes) {
    asm volatile("mbarrier.arrive.expect_tx.shared::cta.b64 _, [%0], %1;"
                 :: "r"(mbar), "r"(bytes) : "memory");
}
// Async remote store into peer CTA's SMEM; data + completion travel together,
// completion counted (in bytes) on the peer's mbarrier. No fence, no arrive.
__device__ __forceinline__ void st_async_u32(uint32_t raddr, uint32_t v, uint32_t rmbar) {
    asm volatile("st.async.shared::cluster.mbarrier::complete_tx::bytes.b32 [%0], %1, [%2];"
                 :: "r"(raddr), "r"(v), "r"(rmbar) : "memory");
}
// Proven acquire wait.
__device__ __forceinline__ void mbar_wait_parity(uint32_t mbar, uint32_t parity) {
    uint32_t done;
    asm volatile(
        "{\n\t.reg .pred p;\n\t"
        "mbarrier.try_wait.parity.acquire.cluster.shared::cta.b64 p, [%1], %2;\n\t"
        "selp.b32 %0, 1, 0, p;\n\t}"
        : "=r"(done) : "r"(mbar), "r"(parity) : "memory");
    if (!done) {
        asm volatile(
            "{\n\t.reg .pred P1;\n\t"
            "WL_%=:\n\t"
            "mbarrier.try_wait.parity.acquire.cluster.shared::cta.b64 P1, [%0], %1, 0x989680;\n\t"
            "@P1 bra.uni WD_%=;\n\t"
            "bra.uni WL_%=;\n\t"
            "WD_%=:\n\t}"
            :: "r"(mbar), "r"(parity) : "memory");
    }
}
__device__ __forceinline__ void cluster_sync() {
    asm volatile("barrier.cluster.arrive.aligned;" ::: "memory");
    asm volatile("barrier.cluster.wait.aligned;" ::: "memory");
}

// Branch-free fast tanh: 1 - 2/(exp(2x)+1). Saturates correctly at +-inf.
__device__ __forceinline__ float tanh_fast(float x) {
    const float e = __expf(2.0f * x);
    return 1.0f - __fdividef(2.0f, e + 1.0f);
}

// ---------------------------------------------------------------------------
// GEMM + bias (R8-proven; ~fp32 SIMT peak): Out[r][j] = In[r]·W[:,j]+bi[j]+bh[j]
// M = 131072, N = K = 256. Tile 128x128x8, 256 threads, 8x8/thread.
__global__ __launch_bounds__(256) void gemm_bias(
        const float* __restrict__ In, const float* __restrict__ W,
        const float* __restrict__ bi, const float* __restrict__ bh,
        float* __restrict__ Out)
{
    __shared__ float As[8][128];
    __shared__ float Bs[8][128];
    const int tid  = threadIdx.x;
    const int mblk = blockIdx.x * 128;
    const int nblk = blockIdx.y * 128;
    const int tx = tid & 15, ty = tid >> 4;

    const int ar = tid >> 1;
    const int ak = (tid & 1) * 4;
    const int bk = tid >> 5;
    const int bc = (tid & 31) * 4;

    const float* Arow = In + (size_t)(mblk + ar) * HH;
    float4 a_next = *(const float4*)(Arow + ak);
    float4 b_next = *(const float4*)(W + (size_t)bk * HH + nblk + bc);

    float acc[8][8];
#pragma unroll
    for (int i = 0; i < 8; i++)
#pragma unroll
        for (int j = 0; j < 8; j++) acc[i][j] = 0.f;

    for (int kt = 0; kt < 32; kt++) {
        As[ak + 0][ar] = a_next.x;
        As[ak + 1][ar] = a_next.y;
        As[ak + 2][ar] = a_next.z;
        As[ak + 3][ar] = a_next.w;
        *(float4*)&Bs[bk][bc] = b_next;
        __syncthreads();
        if (kt < 31) {
            a_next = *(const float4*)(Arow + (kt + 1) * 8 + ak);
            b_next = *(const float4*)(W + (size_t)((kt + 1) * 8 + bk) * HH + nblk + bc);
        }
#pragma unroll
        for (int kk = 0; kk < 8; kk++) {
            float a[8], b[8];
            *(float4*)&a[0] = *(const float4*)&As[kk][ty * 8];
            *(float4*)&a[4] = *(const float4*)&As[kk][ty * 8 + 4];
            *(float4*)&b[0] = *(const float4*)&Bs[kk][tx * 8];
            *(float4*)&b[4] = *(const float4*)&Bs[kk][tx * 8 + 4];
#pragma unroll
            for (int i = 0; i < 8; i++)
#pragma unroll
                for (int j = 0; j < 8; j++) acc[i][j] += a[i] * b[j];
        }
        __syncthreads();
    }

#pragma unroll
    for (int i = 0; i < 8; i++) {
        const size_t r = (size_t)(mblk + ty * 8 + i);
#pragma unroll
        for (int j = 0; j < 8; j += 4) {
            const int c = nblk + tx * 8 + j;
            float4 v;
            v.x = acc[i][j + 0] + bi[c + 0] + bh[c + 0];
            v.y = acc[i][j + 1] + bi[c + 1] + bh[c + 1];
            v.z = acc[i][j + 2] + bi[c + 2] + bh[c + 2];
            v.w = acc[i][j + 3] + bi[c + 3] + bh[c + 3];
            *(float4*)(Out + r * HH + c) = v;
        }
    }
}

// ---------------------------------------------------------------------------
// Recurrence pass (R12-proven structure; tree reduction; earliest-release
// publish order). Cluster of 2 CTAs per batch; CTA rank r owns cols
// [r*128,+128); 256x128 WH slice in registers. Exchange: st.async +
// complete_tx into peer's double-buffered recvbuf; acquire try_wait on
// consumer; expect_tx re-armed race-free (pre-posted for data 0/1; re-arm
// for data t+1 precedes our send of h_t which gates peer's t+1 production).
__global__ __launch_bounds__(256, 1) __cluster_dims__(2, 1, 1)
void rnn_pass(
        const float* __restrict__ Z,    // [B,L,H]
        const float* __restrict__ Wh,   // [H,H]
        const float* __restrict__ h0,   // [B,H]
        float* __restrict__ Out,        // [B,L,H]
        float* __restrict__ hfinal)     // [B,H] or null
{
    const int b     = blockIdx.x >> 1;
    const int half  = blockIdx.x & 1;            // == cluster rank
    const int jbase = half << 7;
    const int peerbase = 128 - jbase;
    const int tid  = threadIdx.x;
    const int w    = tid >> 5;
    const int lane = tid & 31;
    const int j0   = jbase + lane * 4;

    __shared__ float sh_h[256];                  // own half live; peer half only at t=0
    __shared__ float recvbuf[2][128];            // peer halves, double-buffered
    __shared__ float sacc[8 * 128];
    __shared__ uint64_t mbar[2];

    const uint32_t mbar0 = s2u(&mbar[0]);
    const uint32_t mbar1 = s2u(&mbar[1]);
    const uint32_t rb0   = s2u(&recvbuf[0][0]);
    const uint32_t rb1   = s2u(&recvbuf[1][0]);
    const uint32_t prank = (uint32_t)(half ^ 1);
    const uint32_t p_rb[2]   = { mapa_u32(rb0 + (uint32_t)tid * 4u, prank),
                                 mapa_u32(rb1 + (uint32_t)tid * 4u, prank) };
    const uint32_t p_mbar[2] = { mapa_u32(mbar0, prank), mapa_u32(mbar1, prank) };
    const uint32_t l_mbar[2] = { mbar0, mbar1 };

    if (tid == 0) {
        mbar_init(mbar0, 1);                 // 1 arrival = the expect_tx itself
        mbar_init(mbar1, 1);
        mbar_expect_tx(mbar0, 512);          // data 0 (arrives into buf 0)
        mbar_expect_tx(mbar1, 512);          // data 1 (arrives into buf 1)
    }

    // Weight slice: wreg[0] = own k-half rows, wreg[1] = peer k-half rows.
    float4 wreg[2][16];
    const int kb0 = jbase, kb1 = peerbase;
#pragma unroll
    for (int kk = 0; kk < 16; kk++)
        wreg[0][kk] = *(const float4*)(Wh + (size_t)(kb0 + w * 16 + kk) * HH + j0);
#pragma unroll
    for (int kk = 0; kk < 16; kk++)
        wreg[1][kk] = *(const float4*)(Wh + (size_t)(kb1 + w * 16 + kk) * HH + j0);

    sh_h[tid] = h0[b * HH + tid];
    __syncthreads();
    cluster_sync();   // both CTAs' mbarrier init + initial expects visible before any send

    const float4* shh4 = (const float4*)sh_h;

    // Z prefetch (one step ahead)
    float zv = (tid < 128) ? Z[((size_t)b * LL + 0) * HH + jbase + tid] : 0.f;

    for (int t = 0; t < LL; t++) {
        // Prefetch next step's Z while we compute this one.
        float zv_next = 0.f;
        if (t + 1 < LL && tid < 128)
            zv_next = Z[((size_t)b * LL + (t + 1)) * HH + jbase + tid];

        float4 acc = make_float4(0.f, 0.f, 0.f, 0.f);

        // ---- phase 1: own k-half (local, no wait) ----
        {
            float hbuf[16];
            const int b4 = (kb0 + w * 16) >> 2;
            *(float4*)&hbuf[0]  = shh4[b4 + 0];
            *(float4*)&hbuf[4]  = shh4[b4 + 1];
            *(float4*)&hbuf[8]  = shh4[b4 + 2];
            *(float4*)&hbuf[12] = shh4[b4 + 3];
#pragma unroll
            for (int kk = 0; kk < 16; kk++) {
                const float hv = hbuf[kk];
                acc.x += wreg[0][kk].x * hv;
                acc.y += wreg[0][kk].y * hv;
                acc.z += wreg[0][kk].z * hv;
                acc.w += wreg[0][kk].w * hv;
            }
        }

        // ---- wait for peer half of h_{t-1}; re-arm expect for data t+1 ----
        const float4* src;
        if (t > 0) {
            mbar_wait_parity(l_mbar[(t - 1) & 1], ((t - 1) >> 1) & 1);
            // Re-arm this buffer's mbarrier for data t+1. Safe: peer cannot
            // send data t+1 until it has received our h_t, which we send
            // AFTER this point (program order).
            if (t <= LL - 3 && tid == 0)
                mbar_expect_tx(l_mbar[(t - 1) & 1], 512);
            src = (const float4*)&recvbuf[(t - 1) & 1][0];   // indexed by k - peerbase
        } else {
            src = (const float4*)&sh_h[kb1];                  // h0 peer half
        }

        // ---- phase 2: peer k-half ----
        {
            float hbuf[16];
            const int b4 = (w * 16) >> 2;
            *(float4*)&hbuf[0]  = src[b4 + 0];
            *(float4*)&hbuf[4]  = src[b4 + 1];
            *(float4*)&hbuf[8]  = src[b4 + 2];
            *(float4*)&hbuf[12] = src[b4 + 3];
#pragma unroll
            for (int kk = 0; kk < 16; kk++) {
                const float hv = hbuf[kk];
                acc.x += wreg[1][kk].x * hv;
                acc.y += wreg[1][kk].y * hv;
                acc.z += wreg[1][kk].z * hv;
                acc.w += wreg[1][kk].w * hv;
            }
        }

        // ---- cross-warp reduction (3-level tree, ILP) + tanh + publish ----
        *(float4*)&sacc[w * 128 + lane * 4] = acc;
        __syncthreads();
        if (tid < 128) {
            const float p0 = sacc[0 * 128 + tid], p1 = sacc[1 * 128 + tid];
            const float p2 = sacc[2 * 128 + tid], p3 = sacc[3 * 128 + tid];
            const float p4 = sacc[4 * 128 + tid], p5 = sacc[5 * 128 + tid];
            const float p6 = sacc[6 * 128 + tid], p7 = sacc[7 * 128 + tid];
            const float s = (((p0 + p1) + (p2 + p3)) + ((p4 + p5) + (p6 + p7))) + zv;
            const float hv = tanh_fast(s);
            sh_h[jbase + tid] = hv;                                 // 1st: own half for t+1
            if (t < LL - 1)
                st_async_u32(p_rb[t & 1], __float_as_uint(hv),
                             p_mbar[t & 1]);                        // 2nd: async push+complete
            Out[((size_t)b * LL + t) * HH + jbase + tid] = hv;      // 3rd: result (off chain)
        }
        zv = zv_next;
        __syncthreads();   // protects sh_h own-half and sacc reuse
    }

    if (hfinal && tid < 128)
        hfinal[b * HH + jbase + tid] = sh_h[jbase + tid];

    cluster_sync();   // no CTA exits while peer stores may be in flight
}

// ---------------------------------------------------------------------------
extern "C" void kernel_launch(void* const* d_in, const int* in_sizes, int n_in,
                              void* d_out, int out_size) {
    const float* x  = (const float*)d_in[0];   // [B,L,H]
    const float* h0 = (const float*)d_in[1];   // [NL,B,H]
    const float* WI = (const float*)d_in[2];   // [NL,H,H]
    const float* BI = (const float*)d_in[3];   // [NL,H]
    const float* WH = (const float*)d_in[4];   // [NL,H,H]
    const float* BH = (const float*)d_in[5];   // [NL,H]
    float* out = (float*)d_out;

    float *gZ = nullptr, *gH0 = nullptr;
    cudaGetSymbolAddress((void**)&gZ, g_Z);
    cudaGetSymbolAddress((void**)&gH0, g_H0);

    const dim3 ggrid(BB * LL / 128, HH / 128);  // (1024, 2)

    const bool haveMain  = (out_size >= BLH);
    const bool haveFinal = (out_size >= BLH + 2 * BB * HH);
    float* out2 = haveMain ? out : gZ;
    float* hf0  = haveFinal ? (out + BLH) : (haveMain ? nullptr : out);
    float* hf1  = haveFinal ? (out + BLH + BB * HH)
                            : (haveMain ? nullptr : out + BB * HH);

    // Phase A: Z0 = X @ WI0 + BI0 + BH0
    gemm_bias<<<ggrid, 256>>>(x, WI, BI, BH, gZ);
    // Phase B: layer-0 recurrence (64 clusters x 2 CTAs)
    rnn_pass<<<2 * BB, 256>>>(gZ, WH, h0, gH0, hf0);
    // Phase C: Z1 = H0 @ WI1 + BI1 + BH1
    gemm_bias<<<ggrid, 256>>>(gH0, WI + HH * HH, BI + HH, BH + HH, gZ);
    // Phase D: layer-1 recurrence -> output
    rnn_pass<<<2 * BB, 256>>>(gZ, WH + HH * HH, h0 + BB * HH, out2, hf1);
}